// round 5
// baseline (speedup 1.0000x reference)
#include <cuda_runtime.h>
#include <cstdint>

#define N_NODES 50000
#define N_EDGES 1600000
#define NNZ     (N_EDGES + N_NODES)
#define IN_DIM  1024
#define MID_DIM 256
#define MID4    (MID_DIM / 4)   // 64 float4 per row

// ---------------- scratch (static device memory; allocation-free) ----------
__device__ int   g_src[N_EDGES];
__device__ int   g_dst[N_EDGES];
__device__ int   g_cnt[N_NODES];
__device__ int   g_rowptr[N_NODES + 1];
__device__ int   g_fill[N_NODES];
__device__ float g_dis[N_NODES];
__device__ int   g_col[NNZ];
__device__ float g_wgt[NNZ];
__device__ float g_xw[(size_t)N_NODES * MID_DIM];  // xw / agg2 (reused)
__device__ float g_h [(size_t)N_NODES * MID_DIM];  // h
__device__ int   g_flag;                           // 1 = edge_index is int64

// ---------------- setup kernels --------------------------------------------
__global__ void k_init() {
    int i = blockIdx.x * blockDim.x + threadIdx.x;
    if (i < N_NODES) g_cnt[i] = 1;                 // self loop pre-counted
    if (i == 0) g_flag = 1;
}

// int64 little-endian => odd int32 words of small positive values are 0.
__global__ void k_detect(const int* __restrict__ e32) {
    int t = threadIdx.x;
    if (t < 128) {
        if (e32[2 * t + 1] != 0) atomicAnd(&g_flag, 0);
    }
}

__global__ void k_convert(const void* __restrict__ edges) {
    int e = blockIdx.x * blockDim.x + threadIdx.x;
    if (e >= N_EDGES) return;
    int s, d;
    if (g_flag) {
        const long long* p = (const long long*)edges;
        s = (int)p[e];
        d = (int)p[(size_t)N_EDGES + e];
    } else {
        const int* p = (const int*)edges;
        s = p[e];
        d = p[N_EDGES + e];
    }
    g_src[e] = s;
    g_dst[e] = d;
}

__global__ void k_hist() {
    int e = blockIdx.x * blockDim.x + threadIdx.x;
    if (e < N_EDGES) atomicAdd(&g_cnt[g_dst[e]], 1);
}

__global__ void k_dis() {
    int i = blockIdx.x * blockDim.x + threadIdx.x;
    if (i < N_NODES) g_dis[i] = rsqrtf((float)g_cnt[i]);  // deg >= 1 always
}

// single-block exclusive scan of g_cnt -> g_rowptr (50001 entries)
__global__ void k_scan() {
    __shared__ int sums[1024];
    const int t = threadIdx.x;
    const int CH = 49;                       // 49*1024 = 50176 >= 50000
    int base = t * CH;
    int s = 0;
    for (int j = 0; j < CH; j++) {
        int idx = base + j;
        if (idx < N_NODES) s += g_cnt[idx];
    }
    sums[t] = s;
    __syncthreads();
    for (int off = 1; off < 1024; off <<= 1) {
        int v = (t >= off) ? sums[t - off] : 0;
        __syncthreads();
        sums[t] += v;
        __syncthreads();
    }
    int run = (t == 0) ? 0 : sums[t - 1];
    for (int j = 0; j < CH; j++) {
        int idx = base + j;
        if (idx < N_NODES) { g_rowptr[idx] = run; run += g_cnt[idx]; }
    }
    if (t == 1023) g_rowptr[N_NODES] = sums[1023];
}

__global__ void k_self() {
    int i = blockIdx.x * blockDim.x + threadIdx.x;
    if (i >= N_NODES) return;
    int p = g_rowptr[i];
    g_col[p] = i;
    g_wgt[p] = g_dis[i] * g_dis[i];
    g_fill[i] = p + 1;
}

__global__ void k_fill() {
    int e = blockIdx.x * blockDim.x + threadIdx.x;
    if (e >= N_EDGES) return;
    int s = g_src[e], d = g_dst[e];
    int p = atomicAdd(&g_fill[d], 1);
    g_col[p] = s;
    g_wgt[p] = g_dis[s] * g_dis[d];
}

// ---------------- SpMM: out[row] = (relu?)(sum_e w*in[col] (+bias)) --------
// 4 rows per 256-thread CTA; 64 lanes per row; float4 per lane (256 feats).
template<bool RELU>
__global__ void k_spmm(int phase, const float* __restrict__ bias) {
    const float4* __restrict__ in  = (phase == 0) ? (const float4*)g_xw : (const float4*)g_h;
    float4*       __restrict__ out = (phase == 0) ? (float4*)g_h        : (float4*)g_xw;
    int group = threadIdx.x >> 6;
    int lane  = threadIdx.x & 63;
    int row = blockIdx.x * 4 + group;
    if (row >= N_NODES) return;
    int s = g_rowptr[row];
    int e = g_rowptr[row + 1];
    float4 acc = make_float4(0.f, 0.f, 0.f, 0.f);
    int p = s;
    for (; p + 2 <= e; p += 2) {
        int   c0 = g_col[p],   c1 = g_col[p + 1];
        float w0 = g_wgt[p],   w1 = g_wgt[p + 1];
        float4 v0 = in[(size_t)c0 * MID4 + lane];
        float4 v1 = in[(size_t)c1 * MID4 + lane];
        acc.x += w0 * v0.x + w1 * v1.x;
        acc.y += w0 * v0.y + w1 * v1.y;
        acc.z += w0 * v0.z + w1 * v1.z;
        acc.w += w0 * v0.w + w1 * v1.w;
    }
    if (p < e) {
        int c = g_col[p]; float w = g_wgt[p];
        float4 v = in[(size_t)c * MID4 + lane];
        acc.x += w * v.x; acc.y += w * v.y; acc.z += w * v.z; acc.w += w * v.w;
    }
    if (RELU) {
        float4 b = ((const float4*)bias)[lane];
        acc.x = fmaxf(acc.x + b.x, 0.f);
        acc.y = fmaxf(acc.y + b.y, 0.f);
        acc.z = fmaxf(acc.z + b.z, 0.f);
        acc.w = fmaxf(acc.w + b.w, 0.f);
    }
    out[(size_t)row * MID4 + lane] = acc;
}

// ---------------- SGEMM: C = A[MxK] * B[KxN] (+bias), fp32 -----------------
// BM=128, BN=64, BK=16, 256 threads, 8x4 per thread.
// mode 0: A = external (x),  C = g_xw
// mode 1: A = g_xw,          C = external (d_out)
template<bool BIAS>
__global__ void k_sgemm(const float* __restrict__ Aext, const float* __restrict__ B,
                        const float* __restrict__ bias, float* __restrict__ Cext,
                        int M, int N, int K, int mode)
{
    const float* __restrict__ A = (mode == 0) ? Aext : (const float*)g_xw;
    float*       __restrict__ C = (mode == 0) ? (float*)g_xw : Cext;

    __shared__ __align__(16) float As[16][132];   // BK x (BM+4), transposed A tile
    __shared__ __align__(16) float Bs[16][68];    // BK x (BN+4)

    const int tid = threadIdx.x;
    const int tx = tid & 15;        // 16 col-threads * TN=4 = 64
    const int ty = tid >> 4;        // 16 row-threads * TM=8 = 128
    const int rowBase = blockIdx.y * 128;
    const int colBase = blockIdx.x * 64;

    const int aRow = tid >> 2;          // 0..63 (two passes of 64 rows)
    const int aCol = (tid & 3) << 2;    // 0,4,8,12
    const int bRow = tid >> 4;          // 0..15
    const int bCol = (tid & 15) << 2;   // 0..60

    float acc[8][4];
    #pragma unroll
    for (int i = 0; i < 8; i++)
        #pragma unroll
        for (int j = 0; j < 4; j++) acc[i][j] = 0.f;

    for (int kt = 0; kt < K; kt += 16) {
        #pragma unroll
        for (int pass = 0; pass < 2; pass++) {
            int r = aRow + pass * 64;
            int gr = rowBase + r;
            float4 v = make_float4(0.f, 0.f, 0.f, 0.f);
            if (gr < M) v = *(const float4*)(A + (size_t)gr * K + kt + aCol);
            As[aCol + 0][r] = v.x;
            As[aCol + 1][r] = v.y;
            As[aCol + 2][r] = v.z;
            As[aCol + 3][r] = v.w;
        }
        *(float4*)&Bs[bRow][bCol] =
            *(const float4*)(B + (size_t)(kt + bRow) * N + colBase + bCol);
        __syncthreads();

        #pragma unroll
        for (int kk = 0; kk < 16; kk++) {
            float4 a0 = *(const float4*)&As[kk][ty * 8];
            float4 a1 = *(const float4*)&As[kk][ty * 8 + 4];
            float4 bv = *(const float4*)&Bs[kk][tx * 4];
            float a[8] = {a0.x, a0.y, a0.z, a0.w, a1.x, a1.y, a1.z, a1.w};
            float b[4] = {bv.x, bv.y, bv.z, bv.w};
            #pragma unroll
            for (int i = 0; i < 8; i++)
                #pragma unroll
                for (int j = 0; j < 4; j++)
                    acc[i][j] += a[i] * b[j];
        }
        __syncthreads();
    }

    float4 bb = make_float4(0.f, 0.f, 0.f, 0.f);
    if (BIAS) bb = *(const float4*)(bias + colBase + tx * 4);

    #pragma unroll
    for (int i = 0; i < 8; i++) {
        int gr = rowBase + ty * 8 + i;
        if (gr < M) {
            float4 o;
            o.x = acc[i][0] + bb.x;
            o.y = acc[i][1] + bb.y;
            o.z = acc[i][2] + bb.z;
            o.w = acc[i][3] + bb.w;
            *(float4*)(C + (size_t)gr * N + colBase + tx * 4) = o;
        }
    }
}

// ---------------- launch ----------------------------------------------------
extern "C" void kernel_launch(void* const* d_in, const int* in_sizes, int n_in,
                              void* d_out, int out_size) {
    (void)in_sizes; (void)n_in; (void)out_size;
    const float* x  = (const float*)d_in[0];
    const void*  ei = d_in[1];
    const float* W1 = (const float*)d_in[2];
    const float* b1 = (const float*)d_in[3];
    const float* W2 = (const float*)d_in[4];
    const float* b2 = (const float*)d_in[5];
    float* out = (float*)d_out;

    const int TB = 256;
    k_init   <<<(N_NODES + TB - 1) / TB, TB>>>();
    k_detect <<<1, 128>>>((const int*)ei);
    k_convert<<<(N_EDGES + TB - 1) / TB, TB>>>(ei);
    k_hist   <<<(N_EDGES + TB - 1) / TB, TB>>>();
    k_dis    <<<(N_NODES + TB - 1) / TB, TB>>>();
    k_scan   <<<1, 1024>>>();
    k_self   <<<(N_NODES + TB - 1) / TB, TB>>>();
    k_fill   <<<(N_EDGES + TB - 1) / TB, TB>>>();

    // layer 1: xw = x @ W1
    dim3 g1(MID_DIM / 64, (N_NODES + 127) / 128);
    k_sgemm<false><<<g1, 256>>>(x, W1, nullptr, nullptr, N_NODES, MID_DIM, IN_DIM, 0);
    // h = relu(A_hat * xw + b1)
    k_spmm<true> <<<(N_NODES + 3) / 4, 256>>>(0, b1);
    // layer 2 (aggregate-first): agg = A_hat * h  (into g_xw)
    k_spmm<false><<<(N_NODES + 3) / 4, 256>>>(1, nullptr);
    // out = agg @ W2 + b2
    dim3 g2(IN_DIM / 64, (N_NODES + 127) / 128);
    k_sgemm<true> <<<g2, 256>>>(nullptr, W2, b2, out, N_NODES, IN_DIM, MID_DIM, 1);
}

// round 13
// speedup vs baseline: 1.5078x; 1.5078x over previous
#include <cuda_runtime.h>
#include <cuda_bf16.h>
#include <cstdint>

#define N_NODES 50000
#define N_EDGES 1600000
#define NNZ     (N_EDGES + N_NODES)
#define IN_DIM  1024
#define MID_DIM 256
#define MID4    (MID_DIM / 4)

// ---------------- scratch (static device memory; allocation-free) ----------
__device__ int   g_src[N_EDGES];
__device__ int   g_dst[N_EDGES];
__device__ int   g_cnt[N_NODES];
__device__ int   g_rowptr[N_NODES + 1];
__device__ int   g_fill[N_NODES];
__device__ float g_dis[N_NODES];
__device__ int   g_col[NNZ];
__device__ float g_wgt[NNZ];
__device__ float g_xw[(size_t)N_NODES * MID_DIM];  // xw / agg2 (reused)
__device__ float g_h [(size_t)N_NODES * MID_DIM];  // h
__device__ int   g_flag;                           // 1 = edge_index is int64
// bf16-split transposed weights: W1T [256][1024], W2T [1024][256]  (K-major)
__device__ __nv_bfloat16 g_w1t_hi[MID_DIM * IN_DIM];
__device__ __nv_bfloat16 g_w1t_lo[MID_DIM * IN_DIM];
__device__ __nv_bfloat16 g_w2t_hi[IN_DIM * MID_DIM];
__device__ __nv_bfloat16 g_w2t_lo[IN_DIM * MID_DIM];

// ---------------- setup kernels --------------------------------------------
__global__ void k_init() {
    int i = blockIdx.x * blockDim.x + threadIdx.x;
    if (i < N_NODES) g_cnt[i] = 1;                 // self loop pre-counted
    if (i == 0) g_flag = 1;
}

// int64 little-endian => odd int32 words of small positive values are 0.
__global__ void k_detect(const int* __restrict__ e32) {
    int t = threadIdx.x;
    if (t < 128) {
        if (e32[2 * t + 1] != 0) atomicAnd(&g_flag, 0);
    }
}

__global__ void k_convert(const void* __restrict__ edges) {
    int e = blockIdx.x * blockDim.x + threadIdx.x;
    if (e >= N_EDGES) return;
    int s, d;
    if (g_flag) {
        const long long* p = (const long long*)edges;
        s = (int)p[e];
        d = (int)p[(size_t)N_EDGES + e];
    } else {
        const int* p = (const int*)edges;
        s = p[e];
        d = p[N_EDGES + e];
    }
    g_src[e] = s;
    g_dst[e] = d;
}

__global__ void k_hist() {
    int e = blockIdx.x * blockDim.x + threadIdx.x;
    if (e < N_EDGES) atomicAdd(&g_cnt[g_dst[e]], 1);
}

__global__ void k_dis() {
    int i = blockIdx.x * blockDim.x + threadIdx.x;
    if (i < N_NODES) g_dis[i] = rsqrtf((float)g_cnt[i]);
}

__global__ void k_scan() {
    __shared__ int sums[1024];
    const int t = threadIdx.x;
    const int CH = 49;
    int base = t * CH;
    int s = 0;
    for (int j = 0; j < CH; j++) {
        int idx = base + j;
        if (idx < N_NODES) s += g_cnt[idx];
    }
    sums[t] = s;
    __syncthreads();
    for (int off = 1; off < 1024; off <<= 1) {
        int v = (t >= off) ? sums[t - off] : 0;
        __syncthreads();
        sums[t] += v;
        __syncthreads();
    }
    int run = (t == 0) ? 0 : sums[t - 1];
    for (int j = 0; j < CH; j++) {
        int idx = base + j;
        if (idx < N_NODES) { g_rowptr[idx] = run; run += g_cnt[idx]; }
    }
    if (t == 1023) g_rowptr[N_NODES] = sums[1023];
}

__global__ void k_self() {
    int i = blockIdx.x * blockDim.x + threadIdx.x;
    if (i >= N_NODES) return;
    int p = g_rowptr[i];
    g_col[p] = i;
    g_wgt[p] = g_dis[i] * g_dis[i];
    g_fill[i] = p + 1;
}

__global__ void k_fill() {
    int e = blockIdx.x * blockDim.x + threadIdx.x;
    if (e >= N_EDGES) return;
    int s = g_src[e], d = g_dst[e];
    int p = atomicAdd(&g_fill[d], 1);
    g_col[p] = s;
    g_wgt[p] = g_dis[s] * g_dis[d];
}

// Pre-split+transpose weights into bf16 hi/lo, [N][K] K-major.
__global__ void k_prepW1(const float* __restrict__ W1) {   // W1 [1024][256]
    int t = blockIdx.x * blockDim.x + threadIdx.x;
    if (t >= IN_DIM * MID_DIM) return;
    int n = t % MID_DIM, k = t / MID_DIM;
    float v = W1[t];
    __nv_bfloat16 h = __float2bfloat16(v);
    float r = v - __bfloat162float(h);
    g_w1t_hi[(size_t)n * IN_DIM + k] = h;
    g_w1t_lo[(size_t)n * IN_DIM + k] = __float2bfloat16(r);
}
__global__ void k_prepW2(const float* __restrict__ W2) {   // W2 [256][1024]
    int t = blockIdx.x * blockDim.x + threadIdx.x;
    if (t >= IN_DIM * MID_DIM) return;
    int n = t % IN_DIM, k = t / IN_DIM;
    float v = W2[t];
    __nv_bfloat16 h = __float2bfloat16(v);
    float r = v - __bfloat162float(h);
    g_w2t_hi[(size_t)n * MID_DIM + k] = h;
    g_w2t_lo[(size_t)n * MID_DIM + k] = __float2bfloat16(r);
}

// ---------------- SpMM ------------------------------------------------------
template<bool RELU>
__global__ void k_spmm(int phase, const float* __restrict__ bias) {
    const float4* __restrict__ in  = (phase == 0) ? (const float4*)g_xw : (const float4*)g_h;
    float4*       __restrict__ out = (phase == 0) ? (float4*)g_h        : (float4*)g_xw;
    int group = threadIdx.x >> 6;
    int lane  = threadIdx.x & 63;
    int row = blockIdx.x * 4 + group;
    if (row >= N_NODES) return;
    int s = g_rowptr[row];
    int e = g_rowptr[row + 1];
    float4 acc = make_float4(0.f, 0.f, 0.f, 0.f);
    int p = s;
    for (; p + 2 <= e; p += 2) {
        int   c0 = g_col[p],   c1 = g_col[p + 1];
        float w0 = g_wgt[p],   w1 = g_wgt[p + 1];
        float4 v0 = in[(size_t)c0 * MID4 + lane];
        float4 v1 = in[(size_t)c1 * MID4 + lane];
        acc.x += w0 * v0.x + w1 * v1.x;
        acc.y += w0 * v0.y + w1 * v1.y;
        acc.z += w0 * v0.z + w1 * v1.z;
        acc.w += w0 * v0.w + w1 * v1.w;
    }
    if (p < e) {
        int c = g_col[p]; float w = g_wgt[p];
        float4 v = in[(size_t)c * MID4 + lane];
        acc.x += w * v.x; acc.y += w * v.y; acc.z += w * v.z; acc.w += w * v.w;
    }
    if (RELU) {
        float4 b = ((const float4*)bias)[lane];
        acc.x = fmaxf(acc.x + b.x, 0.f);
        acc.y = fmaxf(acc.y + b.y, 0.f);
        acc.z = fmaxf(acc.z + b.z, 0.f);
        acc.w = fmaxf(acc.w + b.w, 0.f);
    }
    out[(size_t)row * MID4 + lane] = acc;
}

// ---------------- mma.sync helpers (family-compatible on sm_103) ------------
__device__ __forceinline__ uint32_t smem_u32(const void* p) {
    uint32_t a;
    asm("{ .reg .u64 t; cvta.to.shared.u64 t, %1; cvt.u32.u64 %0, t; }" : "=r"(a) : "l"(p));
    return a;
}
__device__ __forceinline__ void ldsm4(uint32_t addr, uint32_t* r) {
    asm volatile("ldmatrix.sync.aligned.m8n8.x4.shared.b16 {%0,%1,%2,%3}, [%4];"
        : "=r"(r[0]), "=r"(r[1]), "=r"(r[2]), "=r"(r[3]) : "r"(addr));
}
__device__ __forceinline__ void mma_bf16(float* d, const uint32_t* a, uint32_t b0, uint32_t b1) {
    asm volatile("mma.sync.aligned.m16n8k16.row.col.f32.bf16.bf16.f32 "
        "{%0,%1,%2,%3}, {%4,%5,%6,%7}, {%8,%9}, {%0,%1,%2,%3};"
        : "+f"(d[0]), "+f"(d[1]), "+f"(d[2]), "+f"(d[3])
        : "r"(a[0]), "r"(a[1]), "r"(a[2]), "r"(a[3]), "r"(b0), "r"(b1));
}
__device__ __forceinline__ uint32_t packbf(float a, float b) {
    __nv_bfloat162 t = __floats2bfloat162_rn(a, b);
    return *reinterpret_cast<uint32_t*>(&t);
}

// ---------------- bf16x3 HMMA GEMM ------------------------------------------
// C[M,N] = A[M,K] * W[K,N] (+bias).  Tiles: BM=128, BN=128, BK=32.
// 256 threads = 8 warps (4m x 2n), warp tile 32x64 via m16n8k16.
// Split: D += Ahi*Bhi + Alo*Bhi + Ahi*Blo  (fp32 acc in registers).
// smem rows padded to 40 bf16 (80 B) -> conflict-free ldmatrix.
#define GBM 128
#define GBN 128
#define GBK 32
#define ASTR 40                       // bf16 units per smem row
#define OFF_AHI 0
#define OFF_ALO 10240
#define OFF_BHI 20480
#define OFF_BLO 30720
#define BUFB    40960
#define SMEM_GEMM (2 * BUFB)          // 81920 B

__global__ void __launch_bounds__(256, 1)
k_gemm_mma(const float* __restrict__ Aext, float* __restrict__ Cext,
           const float* __restrict__ bias, int mode)
{
    extern __shared__ char smem[];
    const uint32_t sb = smem_u32(smem);
    const int tid = threadIdx.x;
    const int lid = tid & 31, wid = tid >> 5;
    const int wm = wid & 3, wn = wid >> 2;       // warp tile (wm*32, wn*64)
    const int rowBase = blockIdx.y * GBM;
    const int colBase = blockIdx.x * GBN;

    const float* A; const __nv_bfloat16 *Wh, *Wl;
    int lda, ldb, ldc, K; float* C;
    if (mode == 0) {
        A = Aext; lda = IN_DIM; K = IN_DIM;
        Wh = g_w1t_hi; Wl = g_w1t_lo; ldb = IN_DIM;
        C = g_xw; ldc = MID_DIM;
    } else {
        A = g_xw; lda = MID_DIM; K = MID_DIM;
        Wh = g_w2t_hi; Wl = g_w2t_lo; ldb = MID_DIM;
        C = Cext; ldc = IN_DIM;
    }
    const int nIter = K / GBK;

    // per-thread gmem->smem mapping: row ar (0..127), k-half ah (16 elems)
    const int ar = tid >> 1, ah = tid & 1;
    const int gr = rowBase + ar;
    const bool aValid = (gr < N_NODES);
    const float* Aptr = A + (size_t)gr * lda + ah * 16;
    const __nv_bfloat16* Bhp = Wh + (size_t)(colBase + ar) * ldb + ah * 16;
    const __nv_bfloat16* Blp = Wl + (size_t)(colBase + ar) * ldb + ah * 16;
    const uint32_t stA = (uint32_t)(ar * ASTR + ah * 16) * 2;   // byte offset

    float acc[2][8][4];
#pragma unroll
    for (int i = 0; i < 2; i++)
#pragma unroll
        for (int j = 0; j < 8; j++)
#pragma unroll
            for (int q = 0; q < 4; q++) acc[i][j][q] = 0.f;

    float4 av0, av1, av2, av3;
    uint4 bh0, bh1, bl0, bl1;

#define G_LOAD(IT) do {                                                        \
        int kt = (IT) * GBK;                                                   \
        if (aValid) {                                                          \
            const float4* p = (const float4*)(Aptr + kt);                      \
            av0 = p[0]; av1 = p[1]; av2 = p[2]; av3 = p[3];                    \
        } else {                                                               \
            av0 = av1 = av2 = av3 = make_float4(0.f, 0.f, 0.f, 0.f);           \
        }                                                                      \
        bh0 = *(const uint4*)(Bhp + kt); bh1 = *(const uint4*)(Bhp + kt + 8);  \
        bl0 = *(const uint4*)(Blp + kt); bl1 = *(const uint4*)(Blp + kt + 8);  \
    } while (0)

#define SPLIT4(V, H, L) do {                                                   \
        __nv_bfloat16 h0 = __float2bfloat16((V).x), h1 = __float2bfloat16((V).y), \
                      h2 = __float2bfloat16((V).z), h3 = __float2bfloat16((V).w); \
        (H).x = packbf(0.f, 0.f); /* placeholder overwritten below */          \
        (H).x = ((uint32_t)__bfloat16_as_ushort(h0)) | ((uint32_t)__bfloat16_as_ushort(h1) << 16); \
        (H).y = ((uint32_t)__bfloat16_as_ushort(h2)) | ((uint32_t)__bfloat16_as_ushort(h3) << 16); \
        (L).x = packbf((V).x - __bfloat162float(h0), (V).y - __bfloat162float(h1)); \
        (L).y = packbf((V).z - __bfloat162float(h2), (V).w - __bfloat162float(h3)); \
    } while (0)

#define G_STORE(BUF) do {                                                      \
        char* bptr = smem + (BUF) * BUFB;                                      \
        uint2 H0, L0, H1, L1, H2, L2, H3, L3;                                  \
        SPLIT4(av0, H0, L0); SPLIT4(av1, H1, L1);                              \
        SPLIT4(av2, H2, L2); SPLIT4(av3, H3, L3);                              \
        *(uint4*)(bptr + OFF_AHI + stA)      = make_uint4(H0.x, H0.y, H1.x, H1.y); \
        *(uint4*)(bptr + OFF_AHI + stA + 16) = make_uint4(H2.x, H2.y, H3.x, H3.y); \
        *(uint4*)(bptr + OFF_ALO + stA)      = make_uint4(L0.x, L0.y, L1.x, L1.y); \
        *(uint4*)(bptr + OFF_ALO + stA + 16) = make_uint4(L2.x, L2.y, L3.x, L3.y); \
        *(uint4*)(bptr + OFF_BHI + stA)      = bh0;                            \
        *(uint4*)(bptr + OFF_BHI + stA + 16) = bh1;                            \
        *(uint4*)(bptr + OFF_BLO + stA)      = bl0;                            \
        *(uint4*)(bptr + OFF_BLO + stA + 16) = bl1;                            \
    } while (0)

    // ldmatrix lane address components
    const uint32_t lrow = (lid & 7) + ((lid >> 3) & 1) * 8;    // 0..15
    const uint32_t lcol = (lid >> 4) * 8;                      // bf16 units

    G_LOAD(0);
    for (int it = 0; it < nIter; ++it) {
        const int buf = it & 1;
        G_STORE(buf);
        __syncthreads();
        if (it + 1 < nIter) G_LOAD(it + 1);

        const uint32_t base = sb + buf * BUFB;
#pragma unroll
        for (int kk = 0; kk < 2; ++kk) {
            const uint32_t koff = (kk * 16 + lcol) * 2;
            uint32_t ahi[2][4], alo[2][4];
#pragma unroll
            for (int mi = 0; mi < 2; ++mi) {
                uint32_t ra = base + OFF_AHI
                            + ((uint32_t)(wm * 32 + mi * 16 + lrow) * ASTR) * 2 + koff;
                ldsm4(ra, ahi[mi]);
                ldsm4(ra + (OFF_ALO - OFF_AHI), alo[mi]);
            }
#pragma unroll
            for (int p = 0; p < 4; ++p) {
                uint32_t rb = base + OFF_BHI
                            + ((uint32_t)(wn * 64 + p * 16 + lrow) * ASTR) * 2 + koff;
                uint32_t bh[4], bl[4];
                ldsm4(rb, bh);
                ldsm4(rb + (OFF_BLO - OFF_BHI), bl);
#pragma unroll
                for (int mi = 0; mi < 2; ++mi) {
                    mma_bf16(acc[mi][2 * p],     ahi[mi], bh[0], bh[2]);
                    mma_bf16(acc[mi][2 * p],     alo[mi], bh[0], bh[2]);
                    mma_bf16(acc[mi][2 * p],     ahi[mi], bl[0], bl[2]);
                    mma_bf16(acc[mi][2 * p + 1], ahi[mi], bh[1], bh[3]);
                    mma_bf16(acc[mi][2 * p + 1], alo[mi], bh[1], bh[3]);
                    mma_bf16(acc[mi][2 * p + 1], ahi[mi], bl[1], bl[3]);
                }
            }
        }
        __syncthreads();
    }

    // epilogue: write fp32 acc to C (+bias)
    const bool useBias = (bias != nullptr);
#pragma unroll
    for (int mi = 0; mi < 2; ++mi) {
#pragma unroll
        for (int nj = 0; nj < 8; ++nj) {
            int col = colBase + wn * 64 + nj * 8 + (lid & 3) * 2;
            float b0 = 0.f, b1 = 0.f;
            if (useBias) { b0 = bias[col]; b1 = bias[col + 1]; }
            int row0 = rowBase + wm * 32 + mi * 16 + (lid >> 2);
            if (row0 < N_NODES) {
                float2 o = make_float2(acc[mi][nj][0] + b0, acc[mi][nj][1] + b1);
                *(float2*)(C + (size_t)row0 * ldc + col) = o;
            }
            int row1 = row0 + 8;
            if (row1 < N_NODES) {
                float2 o = make_float2(acc[mi][nj][2] + b0, acc[mi][nj][3] + b1);
                *(float2*)(C + (size_t)row1 * ldc + col) = o;
            }
        }
    }
}

// ---------------- launch ----------------------------------------------------
extern "C" void kernel_launch(void* const* d_in, const int* in_sizes, int n_in,
                              void* d_out, int out_size) {
    (void)in_sizes; (void)n_in; (void)out_size;
    const float* x  = (const float*)d_in[0];
    const void*  ei = d_in[1];
    const float* W1 = (const float*)d_in[2];
    const float* b1 = (const float*)d_in[3];
    const float* W2 = (const float*)d_in[4];
    const float* b2 = (const float*)d_in[5];
    float* out = (float*)d_out;

    cudaFuncSetAttribute(k_gemm_mma, cudaFuncAttributeMaxDynamicSharedMemorySize, SMEM_GEMM);

    const int TB = 256;
    k_init   <<<(N_NODES + TB - 1) / TB, TB>>>();
    k_detect <<<1, 128>>>((const int*)ei);
    k_convert<<<(N_EDGES + TB - 1) / TB, TB>>>(ei);
    k_hist   <<<(N_EDGES + TB - 1) / TB, TB>>>();
    k_dis    <<<(N_NODES + TB - 1) / TB, TB>>>();
    k_scan   <<<1, 1024>>>();
    k_self   <<<(N_NODES + TB - 1) / TB, TB>>>();
    k_fill   <<<(N_EDGES + TB - 1) / TB, TB>>>();
    k_prepW1 <<<(IN_DIM * MID_DIM) / TB, TB>>>(W1);
    k_prepW2 <<<(IN_DIM * MID_DIM) / TB, TB>>>(W2);

    const int MB = (N_NODES + GBM - 1) / GBM;   // 391
    // layer 1: xw = x @ W1  (N=256 -> 2 col tiles; x-major grid => A L2 reuse)
    k_gemm_mma<<<dim3(MID_DIM / GBN, MB), 256, SMEM_GEMM>>>(x, nullptr, nullptr, 0);
    // h = relu(A_hat * xw + b1)
    k_spmm<true> <<<(N_NODES + 3) / 4, 256>>>(0, b1);
    // agg = A_hat * h  (into g_xw)
    k_spmm<false><<<(N_NODES + 3) / 4, 256>>>(1, nullptr);
    // out = agg @ W2 + b2  (N=1024 -> 8 col tiles)
    k_gemm_mma<<<dim3(IN_DIM / GBN, MB), 256, SMEM_GEMM>>>(nullptr, out, b2, 1);
}

// round 15
// speedup vs baseline: 1.7181x; 1.1395x over previous
#include <cuda_runtime.h>
#include <cuda_bf16.h>
#include <cstdint>

#define N_NODES 50000
#define N_EDGES 1600000
#define NNZ     (N_EDGES + N_NODES)
#define IN_DIM  1024
#define MID_DIM 256
#define MID4    (MID_DIM / 4)

// ---------------- scratch (static device memory; allocation-free) ----------
__device__ int   g_src[N_EDGES];
__device__ int   g_dst[N_EDGES];
__device__ int   g_cnt[N_NODES];
__device__ int   g_rowptr[N_NODES + 1];
__device__ int   g_fill[N_NODES];
__device__ float g_dis[N_NODES];
__device__ int2  g_ew[NNZ];                        // (col, wgt bits)
__device__ float g_xw[(size_t)N_NODES * MID_DIM];  // xw / agg2 (reused)
__device__ float g_h [(size_t)N_NODES * MID_DIM];  // h
__device__ int   g_flag;                           // 1 = edge_index is int64
// bf16-split transposed weights: W1T [256][1024], W2T [1024][256]  (K-major)
__device__ __nv_bfloat16 g_w1t_hi[MID_DIM * IN_DIM];
__device__ __nv_bfloat16 g_w1t_lo[MID_DIM * IN_DIM];
__device__ __nv_bfloat16 g_w2t_hi[IN_DIM * MID_DIM];
__device__ __nv_bfloat16 g_w2t_lo[IN_DIM * MID_DIM];

// ---------------- setup kernels --------------------------------------------
__global__ void k_init() {
    int i = blockIdx.x * blockDim.x + threadIdx.x;
    if (i < N_NODES) g_cnt[i] = 1;                 // self loop pre-counted
    if (i == 0) g_flag = 1;
}

// int64 little-endian => odd int32 words of small positive values are 0.
__global__ void k_detect(const int* __restrict__ e32) {
    int t = threadIdx.x;
    if (t < 128) {
        if (e32[2 * t + 1] != 0) atomicAnd(&g_flag, 0);
    }
}

// convert + degree histogram fused
__global__ void k_convert(const void* __restrict__ edges) {
    int e = blockIdx.x * blockDim.x + threadIdx.x;
    if (e >= N_EDGES) return;
    int s, d;
    if (g_flag) {
        const long long* p = (const long long*)edges;
        s = (int)p[e];
        d = (int)p[(size_t)N_EDGES + e];
    } else {
        const int* p = (const int*)edges;
        s = p[e];
        d = p[N_EDGES + e];
    }
    g_src[e] = s;
    g_dst[e] = d;
    atomicAdd(&g_cnt[d], 1);
}

__global__ void k_dis() {
    int i = blockIdx.x * blockDim.x + threadIdx.x;
    if (i < N_NODES) g_dis[i] = rsqrtf((float)g_cnt[i]);
}

__global__ void k_scan() {
    __shared__ int sums[1024];
    const int t = threadIdx.x;
    const int CH = 49;
    int base = t * CH;
    int s = 0;
    for (int j = 0; j < CH; j++) {
        int idx = base + j;
        if (idx < N_NODES) s += g_cnt[idx];
    }
    sums[t] = s;
    __syncthreads();
    for (int off = 1; off < 1024; off <<= 1) {
        int v = (t >= off) ? sums[t - off] : 0;
        __syncthreads();
        sums[t] += v;
        __syncthreads();
    }
    int run = (t == 0) ? 0 : sums[t - 1];
    for (int j = 0; j < CH; j++) {
        int idx = base + j;
        if (idx < N_NODES) { g_rowptr[idx] = run; run += g_cnt[idx]; }
    }
    if (t == 1023) g_rowptr[N_NODES] = sums[1023];
}

__global__ void k_self() {
    int i = blockIdx.x * blockDim.x + threadIdx.x;
    if (i >= N_NODES) return;
    int p = g_rowptr[i];
    float w = g_dis[i] * g_dis[i];
    g_ew[p] = make_int2(i, __float_as_int(w));
    g_fill[i] = p + 1;
}

__global__ void k_fill() {
    int e = blockIdx.x * blockDim.x + threadIdx.x;
    if (e >= N_EDGES) return;
    int s = g_src[e], d = g_dst[e];
    int p = atomicAdd(&g_fill[d], 1);
    float w = g_dis[s] * g_dis[d];
    g_ew[p] = make_int2(s, __float_as_int(w));
}

// Pre-split+transpose weights into bf16 hi/lo, [N][K] K-major.
__global__ void k_prepW1(const float* __restrict__ W1) {   // W1 [1024][256]
    int t = blockIdx.x * blockDim.x + threadIdx.x;
    if (t >= IN_DIM * MID_DIM) return;
    int n = t % MID_DIM, k = t / MID_DIM;
    float v = W1[t];
    __nv_bfloat16 h = __float2bfloat16(v);
    float r = v - __bfloat162float(h);
    g_w1t_hi[(size_t)n * IN_DIM + k] = h;
    g_w1t_lo[(size_t)n * IN_DIM + k] = __float2bfloat16(r);
}
__global__ void k_prepW2(const float* __restrict__ W2) {   // W2 [256][1024]
    int t = blockIdx.x * blockDim.x + threadIdx.x;
    if (t >= IN_DIM * MID_DIM) return;
    int n = t % IN_DIM, k = t / IN_DIM;
    float v = W2[t];
    __nv_bfloat16 h = __float2bfloat16(v);
    float r = v - __bfloat162float(h);
    g_w2t_hi[(size_t)n * MID_DIM + k] = h;
    g_w2t_lo[(size_t)n * MID_DIM + k] = __float2bfloat16(r);
}

// ---------------- SpMM ------------------------------------------------------
template<bool RELU>
__global__ void k_spmm(int phase, const float* __restrict__ bias) {
    const float4* __restrict__ in  = (phase == 0) ? (const float4*)g_xw : (const float4*)g_h;
    float4*       __restrict__ out = (phase == 0) ? (float4*)g_h        : (float4*)g_xw;
    int group = threadIdx.x >> 6;
    int lane  = threadIdx.x & 63;
    int row = blockIdx.x * 4 + group;
    if (row >= N_NODES) return;
    int s = g_rowptr[row];
    int e = g_rowptr[row + 1];
    float4 acc = make_float4(0.f, 0.f, 0.f, 0.f);
    int p = s;
    for (; p + 4 <= e; p += 4) {
        int2 q0 = g_ew[p],     q1 = g_ew[p + 1];
        int2 q2 = g_ew[p + 2], q3 = g_ew[p + 3];
        float4 v0 = in[(size_t)q0.x * MID4 + lane];
        float4 v1 = in[(size_t)q1.x * MID4 + lane];
        float4 v2 = in[(size_t)q2.x * MID4 + lane];
        float4 v3 = in[(size_t)q3.x * MID4 + lane];
        float w0 = __int_as_float(q0.y), w1 = __int_as_float(q1.y);
        float w2 = __int_as_float(q2.y), w3 = __int_as_float(q3.y);
        acc.x += w0 * v0.x + w1 * v1.x + w2 * v2.x + w3 * v3.x;
        acc.y += w0 * v0.y + w1 * v1.y + w2 * v2.y + w3 * v3.y;
        acc.z += w0 * v0.z + w1 * v1.z + w2 * v2.z + w3 * v3.z;
        acc.w += w0 * v0.w + w1 * v1.w + w2 * v2.w + w3 * v3.w;
    }
    for (; p < e; ++p) {
        int2 q = g_ew[p];
        float w = __int_as_float(q.y);
        float4 v = in[(size_t)q.x * MID4 + lane];
        acc.x += w * v.x; acc.y += w * v.y; acc.z += w * v.z; acc.w += w * v.w;
    }
    if (RELU) {
        float4 b = ((const float4*)bias)[lane];
        acc.x = fmaxf(acc.x + b.x, 0.f);
        acc.y = fmaxf(acc.y + b.y, 0.f);
        acc.z = fmaxf(acc.z + b.z, 0.f);
        acc.w = fmaxf(acc.w + b.w, 0.f);
    }
    out[(size_t)row * MID4 + lane] = acc;
}

// ---------------- mma.sync helpers (family-compatible on sm_103) ------------
__device__ __forceinline__ uint32_t smem_u32(const void* p) {
    uint32_t a;
    asm("{ .reg .u64 t; cvta.to.shared.u64 t, %1; cvt.u32.u64 %0, t; }" : "=r"(a) : "l"(p));
    return a;
}
__device__ __forceinline__ void ldsm4(uint32_t addr, uint32_t* r) {
    asm volatile("ldmatrix.sync.aligned.m8n8.x4.shared.b16 {%0,%1,%2,%3}, [%4];"
        : "=r"(r[0]), "=r"(r[1]), "=r"(r[2]), "=r"(r[3]) : "r"(addr));
}
// non-volatile: let ptxas schedule around RAW chains
__device__ __forceinline__ void mma_bf16(float* d, const uint32_t* a, uint32_t b0, uint32_t b1) {
    asm("mma.sync.aligned.m16n8k16.row.col.f32.bf16.bf16.f32 "
        "{%0,%1,%2,%3}, {%4,%5,%6,%7}, {%8,%9}, {%0,%1,%2,%3};"
        : "+f"(d[0]), "+f"(d[1]), "+f"(d[2]), "+f"(d[3])
        : "r"(a[0]), "r"(a[1]), "r"(a[2]), "r"(a[3]), "r"(b0), "r"(b1));
}
__device__ __forceinline__ uint32_t packbf(float a, float b) {
    __nv_bfloat162 t = __floats2bfloat162_rn(a, b);
    return *reinterpret_cast<uint32_t*>(&t);
}
__device__ __forceinline__ void cpasync16(uint32_t dst, const void* src) {
    asm volatile("cp.async.cg.shared.global [%0], [%1], 16;" :: "r"(dst), "l"(src) : "memory");
}
__device__ __forceinline__ void cp_commit() {
    asm volatile("cp.async.commit_group;" ::: "memory");
}
__device__ __forceinline__ void cp_wait0() {
    asm volatile("cp.async.wait_group 0;" ::: "memory");
}

// ---------------- bf16x3 HMMA GEMM ------------------------------------------
// C[M,N] = A[M,K] * W[K,N] (+bias).  Tiles: BM=128, BN=128, BK=32.
// 256 threads = 8 warps (4m x 2n), warp tile 32x64 via m16n8k16.
// Split: D += Ahi*Bhi + Alo*Bhi + Ahi*Blo  (fp32 acc in registers).
// A: gmem->reg (fp32) ->split-> smem.  B: cp.async gmem->smem (pre-split bf16).
// smem rows padded to 40 bf16 (80 B) -> conflict-free ldmatrix.
#define GBM 128
#define GBN 128
#define GBK 32
#define ASTR 40                       // bf16 units per smem row
#define OFF_AHI 0
#define OFF_ALO 10240
#define OFF_BHI 20480
#define OFF_BLO 30720
#define BUFB    40960
#define SMEM_GEMM (2 * BUFB)          // 81920 B

__global__ void __launch_bounds__(256, 2)
k_gemm_mma(const float* __restrict__ Aext, float* __restrict__ Cext,
           const float* __restrict__ bias, int mode)
{
    extern __shared__ char smem[];
    const uint32_t sb = smem_u32(smem);
    const int tid = threadIdx.x;
    const int lid = tid & 31, wid = tid >> 5;
    const int wm = wid & 3, wn = wid >> 2;       // warp tile (wm*32, wn*64)
    const int rowBase = blockIdx.y * GBM;
    const int colBase = blockIdx.x * GBN;

    const float* A; const __nv_bfloat16 *Wh, *Wl;
    int lda, ldb, ldc, K; float* C;
    if (mode == 0) {
        A = Aext; lda = IN_DIM; K = IN_DIM;
        Wh = g_w1t_hi; Wl = g_w1t_lo; ldb = IN_DIM;
        C = g_xw; ldc = MID_DIM;
    } else {
        A = g_xw; lda = MID_DIM; K = MID_DIM;
        Wh = g_w2t_hi; Wl = g_w2t_lo; ldb = MID_DIM;
        C = Cext; ldc = IN_DIM;
    }
    const int nIter = K / GBK;

    // A gmem mapping: row ar (0..127), k-half ah (16 fp32)
    const int ar = tid >> 1, ah = tid & 1;
    const int gr = rowBase + ar;
    const bool aValid = (gr < N_NODES);
    const float* Aptr = A + (size_t)gr * lda + ah * 16;
    const uint32_t stA = (uint32_t)(ar * ASTR + ah * 16) * 2;   // byte offset

    // B cp.async mapping: row br (0..127), 2 adjacent 16B chunks
    const int br = tid >> 1;
    const int cb = (tid & 1) * 2;                 // chunk base (0 or 2)
    const __nv_bfloat16* Bh_src = Wh + (size_t)(colBase + br) * ldb + cb * 8;
    const __nv_bfloat16* Bl_src = Wl + (size_t)(colBase + br) * ldb + cb * 8;
    const uint32_t dstB = (uint32_t)(br * ASTR * 2 + cb * 16); // byte offset in tile

    float acc[2][8][4];
#pragma unroll
    for (int i = 0; i < 2; i++)
#pragma unroll
        for (int j = 0; j < 8; j++)
#pragma unroll
            for (int q = 0; q < 4; q++) acc[i][j][q] = 0.f;

    float4 av0, av1, av2, av3;

#define ISSUE_B(IT, BUF) do {                                                  \
        int kt = (IT) * GBK;                                                   \
        uint32_t bb = sb + (BUF) * BUFB;                                       \
        cpasync16(bb + OFF_BHI + dstB,      Bh_src + kt);                      \
        cpasync16(bb + OFF_BHI + dstB + 16, Bh_src + kt + 8);                  \
        cpasync16(bb + OFF_BLO + dstB,      Bl_src + kt);                      \
        cpasync16(bb + OFF_BLO + dstB + 16, Bl_src + kt + 8);                  \
        cp_commit();                                                           \
    } while (0)

#define A_LOAD(IT) do {                                                        \
        int kt = (IT) * GBK;                                                   \
        if (aValid) {                                                          \
            const float4* p = (const float4*)(Aptr + kt);                      \
            av0 = p[0]; av1 = p[1]; av2 = p[2]; av3 = p[3];                    \
        } else {                                                               \
            av0 = av1 = av2 = av3 = make_float4(0.f, 0.f, 0.f, 0.f);           \
        }                                                                      \
    } while (0)

#define SPLIT4(V, H, L) do {                                                   \
        __nv_bfloat16 h0 = __float2bfloat16((V).x), h1 = __float2bfloat16((V).y), \
                      h2 = __float2bfloat16((V).z), h3 = __float2bfloat16((V).w); \
        (H).x = ((uint32_t)__bfloat16_as_ushort(h0)) | ((uint32_t)__bfloat16_as_ushort(h1) << 16); \
        (H).y = ((uint32_t)__bfloat16_as_ushort(h2)) | ((uint32_t)__bfloat16_as_ushort(h3) << 16); \
        (L).x = packbf((V).x - __bfloat162float(h0), (V).y - __bfloat162float(h1)); \
        (L).y = packbf((V).z - __bfloat162float(h2), (V).w - __bfloat162float(h3)); \
    } while (0)

#define A_STORE(BUF) do {                                                      \
        char* bptr = smem + (BUF) * BUFB;                                      \
        uint2 H0, L0, H1, L1, H2, L2, H3, L3;                                  \
        SPLIT4(av0, H0, L0); SPLIT4(av1, H1, L1);                              \
        SPLIT4(av2, H2, L2); SPLIT4(av3, H3, L3);                              \
        *(uint4*)(bptr + OFF_AHI + stA)      = make_uint4(H0.x, H0.y, H1.x, H1.y); \
        *(uint4*)(bptr + OFF_AHI + stA + 16) = make_uint4(H2.x, H2.y, H3.x, H3.y); \
        *(uint4*)(bptr + OFF_ALO + stA)      = make_uint4(L0.x, L0.y, L1.x, L1.y); \
        *(uint4*)(bptr + OFF_ALO + stA + 16) = make_uint4(L2.x, L2.y, L3.x, L3.y); \
    } while (0)

    // ldmatrix lane address components
    const uint32_t lrow = (lid & 7) + ((lid >> 3) & 1) * 8;    // 0..15
    const uint32_t lcol = (lid >> 4) * 8;                      // bf16 units

    // prologue: stage 0
    ISSUE_B(0, 0);
    A_LOAD(0);
    A_STORE(0);
    cp_wait0();
    __syncthreads();

    for (int it = 0; it < nIter; ++it) {
        const int buf = it & 1;
        const bool more = (it + 1 < nIter);
        if (more) { ISSUE_B(it + 1, buf ^ 1); A_LOAD(it + 1); }

        const uint32_t base = sb + buf * BUFB;
#pragma unroll
        for (int kk = 0; kk < 2; ++kk) {
            const uint32_t koff = (kk * 16 + lcol) * 2;
            uint32_t ahi[2][4], alo[2][4];
#pragma unroll
            for (int mi = 0; mi < 2; ++mi) {
                uint32_t ra = base + OFF_AHI
                            + ((uint32_t)(wm * 32 + mi * 16 + lrow) * ASTR) * 2 + koff;
                ldsm4(ra, ahi[mi]);
                ldsm4(ra + (OFF_ALO - OFF_AHI), alo[mi]);
            }
#pragma unroll
            for (int p = 0; p < 4; ++p) {
                uint32_t rb = base + OFF_BHI
                            + ((uint32_t)(wn * 64 + p * 16 + lrow) * ASTR) * 2 + koff;
                uint32_t bh[4], bl[4];
                ldsm4(rb, bh);
                ldsm4(rb + (OFF_BLO - OFF_BHI), bl);
                // 12 MMAs, same-acc reuse distance = 4
                mma_bf16(acc[0][2 * p],     ahi[0], bh[0], bh[2]);
                mma_bf16(acc[1][2 * p],     ahi[1], bh[0], bh[2]);
                mma_bf16(acc[0][2 * p + 1], ahi[0], bh[1], bh[3]);
                mma_bf16(acc[1][2 * p + 1], ahi[1], bh[1], bh[3]);
                mma_bf16(acc[0][2 * p],     alo[0], bh[0], bh[2]);
                mma_bf16(acc[1][2 * p],     alo[1], bh[0], bh[2]);
                mma_bf16(acc[0][2 * p + 1], alo[0], bh[1], bh[3]);
                mma_bf16(acc[1][2 * p + 1], alo[1], bh[1], bh[3]);
                mma_bf16(acc[0][2 * p],     ahi[0], bl[0], bl[2]);
                mma_bf16(acc[1][2 * p],     ahi[1], bl[0], bl[2]);
                mma_bf16(acc[0][2 * p + 1], ahi[0], bl[1], bl[3]);
                mma_bf16(acc[1][2 * p + 1], ahi[1], bl[1], bl[3]);
            }
        }
        if (more) A_STORE(buf ^ 1);
        cp_wait0();
        __syncthreads();
    }

    // epilogue: write fp32 acc to C (+bias)
    const bool useBias = (bias != nullptr);
#pragma unroll
    for (int mi = 0; mi < 2; ++mi) {
#pragma unroll
        for (int nj = 0; nj < 8; ++nj) {
            int col = colBase + wn * 64 + nj * 8 + (lid & 3) * 2;
            float b0 = 0.f, b1 = 0.f;
            if (useBias) { b0 = bias[col]; b1 = bias[col + 1]; }
            int row0 = rowBase + wm * 32 + mi * 16 + (lid >> 2);
            if (row0 < N_NODES) {
                float2 o = make_float2(acc[mi][nj][0] + b0, acc[mi][nj][1] + b1);
                *(float2*)(C + (size_t)row0 * ldc + col) = o;
            }
            int row1 = row0 + 8;
            if (row1 < N_NODES) {
                float2 o = make_float2(acc[mi][nj][2] + b0, acc[mi][nj][3] + b1);
                *(float2*)(C + (size_t)row1 * ldc + col) = o;
            }
        }
    }
}

// ---------------- launch ----------------------------------------------------
extern "C" void kernel_launch(void* const* d_in, const int* in_sizes, int n_in,
                              void* d_out, int out_size) {
    (void)in_sizes; (void)n_in; (void)out_size;
    const float* x  = (const float*)d_in[0];
    const void*  ei = d_in[1];
    const float* W1 = (const float*)d_in[2];
    const float* b1 = (const float*)d_in[3];
    const float* W2 = (const float*)d_in[4];
    const float* b2 = (const float*)d_in[5];
    float* out = (float*)d_out;

    cudaFuncSetAttribute(k_gemm_mma, cudaFuncAttributeMaxDynamicSharedMemorySize, SMEM_GEMM);

    const int TB = 256;
    k_init   <<<(N_NODES + TB - 1) / TB, TB>>>();
    k_detect <<<1, 128>>>((const int*)ei);
    k_convert<<<(N_EDGES + TB - 1) / TB, TB>>>(ei);
    k_dis    <<<(N_NODES + TB - 1) / TB, TB>>>();
    k_scan   <<<1, 1024>>>();
    k_self   <<<(N_NODES + TB - 1) / TB, TB>>>();
    k_fill   <<<(N_EDGES + TB - 1) / TB, TB>>>();
    k_prepW1 <<<(IN_DIM * MID_DIM) / TB, TB>>>(W1);
    k_prepW2 <<<(IN_DIM * MID_DIM) / TB, TB>>>(W2);

    const int MB = (N_NODES + GBM - 1) / GBM;   // 391
    // layer 1: xw = x @ W1  (N=256 -> 2 col tiles; x-major grid => A L2 reuse)
    k_gemm_mma<<<dim3(MID_DIM / GBN, MB), 256, SMEM_GEMM>>>(x, nullptr, nullptr, 0);
    // h = relu(A_hat * xw + b1)
    k_spmm<true> <<<(N_NODES + 3) / 4, 256>>>(0, b1);
    // agg = A_hat * h  (into g_xw)
    k_spmm<false><<<(N_NODES + 3) / 4, 256>>>(1, nullptr);
    // out = agg @ W2 + b2  (N=1024 -> 8 col tiles)
    k_gemm_mma<<<dim3(IN_DIM / GBN, MB), 256, SMEM_GEMM>>>(nullptr, out, b2, 1);
}

// round 16
// speedup vs baseline: 1.8044x; 1.0502x over previous
#include <cuda_runtime.h>
#include <cuda_bf16.h>
#include <cstdint>

#define N_NODES 50000
#define N_EDGES 1600000
#define NNZ     (N_EDGES + N_NODES)
#define IN_DIM  1024
#define MID_DIM 256
#define MID4    (MID_DIM / 4)

// ---------------- scratch (static device memory; allocation-free) ----------
__device__ int   g_cnt[N_NODES];
__device__ int   g_rowptr[N_NODES + 1];
__device__ int   g_fill[N_NODES];
__device__ float g_dis[N_NODES];
__device__ int2  g_ew[NNZ];                        // (col, wgt bits)
__device__ float g_xw[(size_t)N_NODES * MID_DIM];  // xw / agg2 (reused)
__device__ float g_h [(size_t)N_NODES * MID_DIM];  // h
__device__ int   g_flag;                           // 1 = edge_index is int64
// bf16-split transposed weights: W1T [256][1024], W2T [1024][256]  (K-major)
__device__ __nv_bfloat16 g_w1t_hi[MID_DIM * IN_DIM];
__device__ __nv_bfloat16 g_w1t_lo[MID_DIM * IN_DIM];
__device__ __nv_bfloat16 g_w2t_hi[IN_DIM * MID_DIM];
__device__ __nv_bfloat16 g_w2t_lo[IN_DIM * MID_DIM];

// side stream + fork/join events, created once at load (no device-mem alloc).
struct HxSide {
    cudaStream_t s = nullptr;
    cudaEvent_t  f = nullptr, j = nullptr;
    bool ok = false;
    HxSide() {
        if (cudaStreamCreateWithFlags(&s, cudaStreamNonBlocking) != cudaSuccess) return;
        if (cudaEventCreateWithFlags(&f, cudaEventDisableTiming) != cudaSuccess) return;
        if (cudaEventCreateWithFlags(&j, cudaEventDisableTiming) != cudaSuccess) return;
        ok = true;
    }
};
static HxSide hx;

// ---------------- setup kernels --------------------------------------------
__global__ void k_init() {
    int i = blockIdx.x * blockDim.x + threadIdx.x;
    if (i < N_NODES) g_cnt[i] = 1;                 // self loop pre-counted
    if (i == 0) g_flag = 1;
}

// int64 little-endian => odd int32 words of small positive values are 0.
__global__ void k_detect(const int* __restrict__ e32) {
    int t = threadIdx.x;
    if (t < 128) {
        if (e32[2 * t + 1] != 0) atomicAnd(&g_flag, 0);
    }
}

// degree histogram straight off the edge tensor (dst half only)
__global__ void k_hist(const void* __restrict__ edges) {
    int e = blockIdx.x * blockDim.x + threadIdx.x;
    if (e >= N_EDGES) return;
    int d;
    if (g_flag) d = (int)((const long long*)edges)[(size_t)N_EDGES + e];
    else        d = ((const int*)edges)[N_EDGES + e];
    atomicAdd(&g_cnt[d], 1);
}

__global__ void k_dis() {
    int i = blockIdx.x * blockDim.x + threadIdx.x;
    if (i < N_NODES) g_dis[i] = rsqrtf((float)g_cnt[i]);
}

__global__ void k_scan() {
    __shared__ int sums[1024];
    const int t = threadIdx.x;
    const int CH = 49;
    int base = t * CH;
    int s = 0;
    for (int j = 0; j < CH; j++) {
        int idx = base + j;
        if (idx < N_NODES) s += g_cnt[idx];
    }
    sums[t] = s;
    __syncthreads();
    for (int off = 1; off < 1024; off <<= 1) {
        int v = (t >= off) ? sums[t - off] : 0;
        __syncthreads();
        sums[t] += v;
        __syncthreads();
    }
    int run = (t == 0) ? 0 : sums[t - 1];
    for (int j = 0; j < CH; j++) {
        int idx = base + j;
        if (idx < N_NODES) { g_rowptr[idx] = run; run += g_cnt[idx]; }
    }
    if (t == 1023) g_rowptr[N_NODES] = sums[1023];
}

__global__ void k_self() {
    int i = blockIdx.x * blockDim.x + threadIdx.x;
    if (i >= N_NODES) return;
    int p = g_rowptr[i];
    float w = g_dis[i] * g_dis[i];
    g_ew[p] = make_int2(i, __float_as_int(w));
    g_fill[i] = p + 1;
}

__global__ void k_fill(const void* __restrict__ edges) {
    int e = blockIdx.x * blockDim.x + threadIdx.x;
    if (e >= N_EDGES) return;
    int s, d;
    if (g_flag) {
        const long long* p = (const long long*)edges;
        s = (int)p[e];
        d = (int)p[(size_t)N_EDGES + e];
    } else {
        const int* p = (const int*)edges;
        s = p[e];
        d = p[N_EDGES + e];
    }
    int p = atomicAdd(&g_fill[d], 1);
    float w = g_dis[s] * g_dis[d];
    g_ew[p] = make_int2(s, __float_as_int(w));
}

// Pre-split+transpose weights into bf16 hi/lo, [N][K] K-major.
__global__ void k_prepW1(const float* __restrict__ W1) {   // W1 [1024][256]
    int t = blockIdx.x * blockDim.x + threadIdx.x;
    if (t >= IN_DIM * MID_DIM) return;
    int n = t % MID_DIM, k = t / MID_DIM;
    float v = W1[t];
    __nv_bfloat16 h = __float2bfloat16(v);
    float r = v - __bfloat162float(h);
    g_w1t_hi[(size_t)n * IN_DIM + k] = h;
    g_w1t_lo[(size_t)n * IN_DIM + k] = __float2bfloat16(r);
}
__global__ void k_prepW2(const float* __restrict__ W2) {   // W2 [256][1024]
    int t = blockIdx.x * blockDim.x + threadIdx.x;
    if (t >= IN_DIM * MID_DIM) return;
    int n = t % IN_DIM, k = t / IN_DIM;
    float v = W2[t];
    __nv_bfloat16 h = __float2bfloat16(v);
    float r = v - __bfloat162float(h);
    g_w2t_hi[(size_t)n * MID_DIM + k] = h;
    g_w2t_lo[(size_t)n * MID_DIM + k] = __float2bfloat16(r);
}

// ---------------- SpMM ------------------------------------------------------
template<bool RELU>
__global__ void k_spmm(int phase, const float* __restrict__ bias) {
    const float4* __restrict__ in  = (phase == 0) ? (const float4*)g_xw : (const float4*)g_h;
    float4*       __restrict__ out = (phase == 0) ? (float4*)g_h        : (float4*)g_xw;
    int group = threadIdx.x >> 6;
    int lane  = threadIdx.x & 63;
    int row = blockIdx.x * 4 + group;
    if (row >= N_NODES) return;
    int s = g_rowptr[row];
    int e = g_rowptr[row + 1];
    float4 acc = make_float4(0.f, 0.f, 0.f, 0.f);
    int p = s;
    for (; p + 4 <= e; p += 4) {
        int2 q0 = g_ew[p],     q1 = g_ew[p + 1];
        int2 q2 = g_ew[p + 2], q3 = g_ew[p + 3];
        float4 v0 = in[(size_t)q0.x * MID4 + lane];
        float4 v1 = in[(size_t)q1.x * MID4 + lane];
        float4 v2 = in[(size_t)q2.x * MID4 + lane];
        float4 v3 = in[(size_t)q3.x * MID4 + lane];
        float w0 = __int_as_float(q0.y), w1 = __int_as_float(q1.y);
        float w2 = __int_as_float(q2.y), w3 = __int_as_float(q3.y);
        acc.x += w0 * v0.x + w1 * v1.x + w2 * v2.x + w3 * v3.x;
        acc.y += w0 * v0.y + w1 * v1.y + w2 * v2.y + w3 * v3.y;
        acc.z += w0 * v0.z + w1 * v1.z + w2 * v2.z + w3 * v3.z;
        acc.w += w0 * v0.w + w1 * v1.w + w2 * v2.w + w3 * v3.w;
    }
    for (; p < e; ++p) {
        int2 q = g_ew[p];
        float w = __int_as_float(q.y);
        float4 v = in[(size_t)q.x * MID4 + lane];
        acc.x += w * v.x; acc.y += w * v.y; acc.z += w * v.z; acc.w += w * v.w;
    }
    if (RELU) {
        float4 b = ((const float4*)bias)[lane];
        acc.x = fmaxf(acc.x + b.x, 0.f);
        acc.y = fmaxf(acc.y + b.y, 0.f);
        acc.z = fmaxf(acc.z + b.z, 0.f);
        acc.w = fmaxf(acc.w + b.w, 0.f);
    }
    out[(size_t)row * MID4 + lane] = acc;
}

// ---------------- mma.sync helpers (family-compatible on sm_103) ------------
__device__ __forceinline__ uint32_t smem_u32(const void* p) {
    uint32_t a;
    asm("{ .reg .u64 t; cvta.to.shared.u64 t, %1; cvt.u32.u64 %0, t; }" : "=r"(a) : "l"(p));
    return a;
}
__device__ __forceinline__ void ldsm4(uint32_t addr, uint32_t* r) {
    asm volatile("ldmatrix.sync.aligned.m8n8.x4.shared.b16 {%0,%1,%2,%3}, [%4];"
        : "=r"(r[0]), "=r"(r[1]), "=r"(r[2]), "=r"(r[3]) : "r"(addr));
}
__device__ __forceinline__ void mma_bf16(float* d, const uint32_t* a, uint32_t b0, uint32_t b1) {
    asm("mma.sync.aligned.m16n8k16.row.col.f32.bf16.bf16.f32 "
        "{%0,%1,%2,%3}, {%4,%5,%6,%7}, {%8,%9}, {%0,%1,%2,%3};"
        : "+f"(d[0]), "+f"(d[1]), "+f"(d[2]), "+f"(d[3])
        : "r"(a[0]), "r"(a[1]), "r"(a[2]), "r"(a[3]), "r"(b0), "r"(b1));
}
__device__ __forceinline__ uint32_t packbf(float a, float b) {
    __nv_bfloat162 t = __floats2bfloat162_rn(a, b);
    return *reinterpret_cast<uint32_t*>(&t);
}
__device__ __forceinline__ void cpasync16(uint32_t dst, const void* src) {
    asm volatile("cp.async.cg.shared.global [%0], [%1], 16;" :: "r"(dst), "l"(src) : "memory");
}
__device__ __forceinline__ void cp_commit() {
    asm volatile("cp.async.commit_group;" ::: "memory");
}
__device__ __forceinline__ void cp_wait0() {
    asm volatile("cp.async.wait_group 0;" ::: "memory");
}

// ---------------- bf16x3 HMMA GEMM ------------------------------------------
#define GBM 128
#define GBN 128
#define GBK 32
#define ASTR 40                       // bf16 units per smem row
#define OFF_AHI 0
#define OFF_ALO 10240
#define OFF_BHI 20480
#define OFF_BLO 30720
#define BUFB    40960
#define SMEM_GEMM (2 * BUFB)          // 81920 B

__global__ void __launch_bounds__(256, 2)
k_gemm_mma(const float* __restrict__ Aext, float* __restrict__ Cext,
           const float* __restrict__ bias, int mode)
{
    extern __shared__ char smem[];
    const uint32_t sb = smem_u32(smem);
    const int tid = threadIdx.x;
    const int lid = tid & 31, wid = tid >> 5;
    const int wm = wid & 3, wn = wid >> 2;       // warp tile (wm*32, wn*64)
    const int rowBase = blockIdx.y * GBM;
    const int colBase = blockIdx.x * GBN;

    const float* A; const __nv_bfloat16 *Wh, *Wl;
    int lda, ldb, ldc, K; float* C;
    if (mode == 0) {
        A = Aext; lda = IN_DIM; K = IN_DIM;
        Wh = g_w1t_hi; Wl = g_w1t_lo; ldb = IN_DIM;
        C = g_xw; ldc = MID_DIM;
    } else {
        A = g_xw; lda = MID_DIM; K = MID_DIM;
        Wh = g_w2t_hi; Wl = g_w2t_lo; ldb = MID_DIM;
        C = Cext; ldc = IN_DIM;
    }
    const int nIter = K / GBK;

    const int ar = tid >> 1, ah = tid & 1;
    const int gr = rowBase + ar;
    const bool aValid = (gr < N_NODES);
    const float* Aptr = A + (size_t)gr * lda + ah * 16;
    const uint32_t stA = (uint32_t)(ar * ASTR + ah * 16) * 2;

    const int br = tid >> 1;
    const int cb = (tid & 1) * 2;
    const __nv_bfloat16* Bh_src = Wh + (size_t)(colBase + br) * ldb + cb * 8;
    const __nv_bfloat16* Bl_src = Wl + (size_t)(colBase + br) * ldb + cb * 8;
    const uint32_t dstB = (uint32_t)(br * ASTR * 2 + cb * 16);

    float acc[2][8][4];
#pragma unroll
    for (int i = 0; i < 2; i++)
#pragma unroll
        for (int j = 0; j < 8; j++)
#pragma unroll
            for (int q = 0; q < 4; q++) acc[i][j][q] = 0.f;

    float4 av0, av1, av2, av3;

#define ISSUE_B(IT, BUF) do {                                                  \
        int kt = (IT) * GBK;                                                   \
        uint32_t bb = sb + (BUF) * BUFB;                                       \
        cpasync16(bb + OFF_BHI + dstB,      Bh_src + kt);                      \
        cpasync16(bb + OFF_BHI + dstB + 16, Bh_src + kt + 8);                  \
        cpasync16(bb + OFF_BLO + dstB,      Bl_src + kt);                      \
        cpasync16(bb + OFF_BLO + dstB + 16, Bl_src + kt + 8);                  \
        cp_commit();                                                           \
    } while (0)

#define A_LOAD(IT) do {                                                        \
        int kt = (IT) * GBK;                                                   \
        if (aValid) {                                                          \
            const float4* p = (const float4*)(Aptr + kt);                      \
            av0 = p[0]; av1 = p[1]; av2 = p[2]; av3 = p[3];                    \
        } else {                                                               \
            av0 = av1 = av2 = av3 = make_float4(0.f, 0.f, 0.f, 0.f);           \
        }                                                                      \
    } while (0)

#define SPLIT4(V, H, L) do {                                                   \
        __nv_bfloat16 h0 = __float2bfloat16((V).x), h1 = __float2bfloat16((V).y), \
                      h2 = __float2bfloat16((V).z), h3 = __float2bfloat16((V).w); \
        (H).x = ((uint32_t)__bfloat16_as_ushort(h0)) | ((uint32_t)__bfloat16_as_ushort(h1) << 16); \
        (H).y = ((uint32_t)__bfloat16_as_ushort(h2)) | ((uint32_t)__bfloat16_as_ushort(h3) << 16); \
        (L).x = packbf((V).x - __bfloat162float(h0), (V).y - __bfloat162float(h1)); \
        (L).y = packbf((V).z - __bfloat162float(h2), (V).w - __bfloat162float(h3)); \
    } while (0)

#define A_STORE(BUF) do {                                                      \
        char* bptr = smem + (BUF) * BUFB;                                      \
        uint2 H0, L0, H1, L1, H2, L2, H3, L3;                                  \
        SPLIT4(av0, H0, L0); SPLIT4(av1, H1, L1);                              \
        SPLIT4(av2, H2, L2); SPLIT4(av3, H3, L3);                              \
        *(uint4*)(bptr + OFF_AHI + stA)      = make_uint4(H0.x, H0.y, H1.x, H1.y); \
        *(uint4*)(bptr + OFF_AHI + stA + 16) = make_uint4(H2.x, H2.y, H3.x, H3.y); \
        *(uint4*)(bptr + OFF_ALO + stA)      = make_uint4(L0.x, L0.y, L1.x, L1.y); \
        *(uint4*)(bptr + OFF_ALO + stA + 16) = make_uint4(L2.x, L2.y, L3.x, L3.y); \
    } while (0)

    const uint32_t lrow = (lid & 7) + ((lid >> 3) & 1) * 8;
    const uint32_t lcol = (lid >> 4) * 8;

    ISSUE_B(0, 0);
    A_LOAD(0);
    A_STORE(0);
    cp_wait0();
    __syncthreads();

    for (int it = 0; it < nIter; ++it) {
        const int buf = it & 1;
        const bool more = (it + 1 < nIter);
        if (more) { ISSUE_B(it + 1, buf ^ 1); A_LOAD(it + 1); }

        const uint32_t base = sb + buf * BUFB;
#pragma unroll
        for (int kk = 0; kk < 2; ++kk) {
            const uint32_t koff = (kk * 16 + lcol) * 2;
            uint32_t ahi[2][4], alo[2][4];
#pragma unroll
            for (int mi = 0; mi < 2; ++mi) {
                uint32_t ra = base + OFF_AHI
                            + ((uint32_t)(wm * 32 + mi * 16 + lrow) * ASTR) * 2 + koff;
                ldsm4(ra, ahi[mi]);
                ldsm4(ra + (OFF_ALO - OFF_AHI), alo[mi]);
            }
#pragma unroll
            for (int p = 0; p < 4; ++p) {
                uint32_t rb = base + OFF_BHI
                            + ((uint32_t)(wn * 64 + p * 16 + lrow) * ASTR) * 2 + koff;
                uint32_t bh[4], bl[4];
                ldsm4(rb, bh);
                ldsm4(rb + (OFF_BLO - OFF_BHI), bl);
                mma_bf16(acc[0][2 * p],     ahi[0], bh[0], bh[2]);
                mma_bf16(acc[1][2 * p],     ahi[1], bh[0], bh[2]);
                mma_bf16(acc[0][2 * p + 1], ahi[0], bh[1], bh[3]);
                mma_bf16(acc[1][2 * p + 1], ahi[1], bh[1], bh[3]);
                mma_bf16(acc[0][2 * p],     alo[0], bh[0], bh[2]);
                mma_bf16(acc[1][2 * p],     alo[1], bh[0], bh[2]);
                mma_bf16(acc[0][2 * p + 1], alo[0], bh[1], bh[3]);
                mma_bf16(acc[1][2 * p + 1], alo[1], bh[1], bh[3]);
                mma_bf16(acc[0][2 * p],     ahi[0], bl[0], bl[2]);
                mma_bf16(acc[1][2 * p],     ahi[1], bl[0], bl[2]);
                mma_bf16(acc[0][2 * p + 1], ahi[0], bl[1], bl[3]);
                mma_bf16(acc[1][2 * p + 1], ahi[1], bl[1], bl[3]);
            }
        }
        if (more) A_STORE(buf ^ 1);
        cp_wait0();
        __syncthreads();
    }

    const bool useBias = (bias != nullptr);
#pragma unroll
    for (int mi = 0; mi < 2; ++mi) {
#pragma unroll
        for (int nj = 0; nj < 8; ++nj) {
            int col = colBase + wn * 64 + nj * 8 + (lid & 3) * 2;
            float b0 = 0.f, b1 = 0.f;
            if (useBias) { b0 = bias[col]; b1 = bias[col + 1]; }
            int row0 = rowBase + wm * 32 + mi * 16 + (lid >> 2);
            if (row0 < N_NODES) {
                float2 o = make_float2(acc[mi][nj][0] + b0, acc[mi][nj][1] + b1);
                *(float2*)(C + (size_t)row0 * ldc + col) = o;
            }
            int row1 = row0 + 8;
            if (row1 < N_NODES) {
                float2 o = make_float2(acc[mi][nj][2] + b0, acc[mi][nj][3] + b1);
                *(float2*)(C + (size_t)row1 * ldc + col) = o;
            }
        }
    }
}

// ---------------- launch ----------------------------------------------------
extern "C" void kernel_launch(void* const* d_in, const int* in_sizes, int n_in,
                              void* d_out, int out_size) {
    (void)in_sizes; (void)n_in; (void)out_size;
    const float* x  = (const float*)d_in[0];
    const void*  ei = d_in[1];
    const float* W1 = (const float*)d_in[2];
    const float* b1 = (const float*)d_in[3];
    const float* W2 = (const float*)d_in[4];
    const float* b2 = (const float*)d_in[5];
    float* out = (float*)d_out;

    cudaFuncSetAttribute(k_gemm_mma, cudaFuncAttributeMaxDynamicSharedMemorySize, SMEM_GEMM);

    const int TB = 256;
    const bool fork = hx.ok;
    cudaStream_t side = fork ? hx.s : (cudaStream_t)0;

    // fork: CSR-build branch runs concurrently with prepW+GEMM1
    if (fork) {
        cudaEventRecord(hx.f, 0);
        cudaStreamWaitEvent(side, hx.f, 0);
    }

    // --- side branch: CSR build ---
    k_init   <<<(N_NODES + TB - 1) / TB, TB, 0, side>>>();
    k_detect <<<1, 128, 0, side>>>((const int*)ei);
    k_hist   <<<(N_EDGES + TB - 1) / TB, TB, 0, side>>>(ei);
    k_dis    <<<(N_NODES + TB - 1) / TB, TB, 0, side>>>();
    k_scan   <<<1, 1024, 0, side>>>();
    k_self   <<<(N_NODES + TB - 1) / TB, TB, 0, side>>>();
    k_fill   <<<(N_EDGES + TB - 1) / TB, TB, 0, side>>>(ei);

    // --- main branch: weight prep + GEMM1 ---
    k_prepW1 <<<(IN_DIM * MID_DIM) / TB, TB>>>(W1);
    k_prepW2 <<<(IN_DIM * MID_DIM) / TB, TB>>>(W2);
    const int MB = (N_NODES + GBM - 1) / GBM;   // 391
    k_gemm_mma<<<dim3(MID_DIM / GBN, MB), 256, SMEM_GEMM>>>(x, nullptr, nullptr, 0);

    // join before SpMM1 (needs CSR + xw)
    if (fork) {
        cudaEventRecord(hx.j, side);
        cudaStreamWaitEvent(0, hx.j, 0);
    }

    k_spmm<true> <<<(N_NODES + 3) / 4, 256>>>(0, b1);
    k_spmm<false><<<(N_NODES + 3) / 4, 256>>>(1, nullptr);
    k_gemm_mma<<<dim3(IN_DIM / GBN, MB), 256, SMEM_GEMM>>>(nullptr, out, b2, 1);
}